// round 15
// baseline (speedup 1.0000x reference)
#include <cuda_runtime.h>
#include <math.h>

#define Bq 32
#define Sq 512
#define Eq 256
#define Hq 512
#define Lq 48
#define Mq (Bq*Sq)

// ---------------- scratch ----------------
__device__ __align__(16) float g_XW[2][Mq][2048];
__device__ __align__(16) float g_H[2][Bq][Sq + 1][Hq];      // for emission
__device__ __align__(16) float g_Ht[2][Sq + 1][Hq][Bq];     // transposed, recurrence staging
__device__ __align__(16) float g_E[Mq][Lq];
__device__ float g_vpart[Bq][8][Lq];
__device__ unsigned g_bar[2];

// ---------------- init ----------------
__global__ void init_kernel() {
    int idx = blockIdx.x * blockDim.x + threadIdx.x;
    ((float*)g_Ht[0][0])[idx]  = 0.f;
    ((float*)g_Ht[1][Sq])[idx] = 0.f;
    if (idx < 2) g_bar[idx] = 0u;
}

// ---------------- K1: embed-gather + input projection ----------------
// 128m x 64g tile, 256 threads, 8x4 thread tile, K chunks of 32.
__global__ __launch_bounds__(256) void proj_kernel(
    const int* __restrict__ tokens, const float* __restrict__ embed,
    const float* __restrict__ w_ih_f, const float* __restrict__ b_f,
    const float* __restrict__ w_ih_b, const float* __restrict__ b_b)
{
    __shared__ float xs[32 * 128];   // [k][m]
    __shared__ float ws[32 * 64];    // [k][g]
    __shared__ int toks[128];
    int dir = blockIdx.z;
    const float* w = dir ? w_ih_b : w_ih_f;
    const float* bias = dir ? b_b : b_f;
    int m0 = blockIdx.x * 128, g0 = blockIdx.y * 64;
    int tid = threadIdx.x;
    if (tid < 128) toks[tid] = tokens[m0 + tid];
    int tx = tid & 15, ty = tid >> 4;
    float acc[8][4];
#pragma unroll
    for (int a = 0; a < 8; a++)
#pragma unroll
        for (int c = 0; c < 4; c++) acc[a][c] = 0.f;
    for (int kc = 0; kc < 8; kc++) {
        __syncthreads();
        for (int q = tid; q < 1024; q += 256) {
            int ml = q >> 3, k4 = q & 7;
            float4 v = *(const float4*)&embed[toks[ml] * Eq + kc * 32 + k4 * 4];
            xs[(k4 * 4 + 0) * 128 + ml] = v.x; xs[(k4 * 4 + 1) * 128 + ml] = v.y;
            xs[(k4 * 4 + 2) * 128 + ml] = v.z; xs[(k4 * 4 + 3) * 128 + ml] = v.w;
        }
        for (int q = tid; q < 512; q += 256) {
            int gl = q >> 3, k4 = q & 7;
            float4 v = *(const float4*)&w[(g0 + gl) * Eq + kc * 32 + k4 * 4];
            ws[(k4 * 4 + 0) * 64 + gl] = v.x; ws[(k4 * 4 + 1) * 64 + gl] = v.y;
            ws[(k4 * 4 + 2) * 64 + gl] = v.z; ws[(k4 * 4 + 3) * 64 + gl] = v.w;
        }
        __syncthreads();
        const float4* xs4 = (const float4*)xs;
        const float4* ws4 = (const float4*)ws;
#pragma unroll 4
        for (int k = 0; k < 32; k++) {
            float4 x0 = xs4[k * 32 + tx];
            float4 x1 = xs4[k * 32 + 16 + tx];
            float4 wv = ws4[k * 16 + ty];
            float xr[8] = {x0.x, x0.y, x0.z, x0.w, x1.x, x1.y, x1.z, x1.w};
            float wr[4] = {wv.x, wv.y, wv.z, wv.w};
#pragma unroll
            for (int a = 0; a < 8; a++)
#pragma unroll
                for (int c = 0; c < 4; c++)
                    acc[a][c] = fmaf(xr[a], wr[c], acc[a][c]);
        }
    }
#pragma unroll
    for (int a = 0; a < 8; a++) {
        int m = m0 + (a < 4 ? tx * 4 + a : 64 + tx * 4 + (a - 4));
        int g = g0 + ty * 4;
        float4 o;
        o.x = acc[a][0] + bias[g + 0]; o.y = acc[a][1] + bias[g + 1];
        o.z = acc[a][2] + bias[g + 2]; o.w = acc[a][3] + bias[g + 3];
        *(float4*)&g_XW[dir][m][g] = o;
    }
}

// ---------------- K2: persistent bi-LSTM recurrence ----------------
// 128 CTAs (64 j-tiles x 2 dirs), 256 threads, 128 KB smem, per-dir barrier.
// Thread = (batch b, unit jl): owns all 4 gate rows -> no smem shuffle.
__global__ __launch_bounds__(256) void lstm_persist(
    const float* __restrict__ w_hh_f, const float* __restrict__ w_hh_b)
{
    extern __shared__ float sm[];
    float* hs = sm;              // [k][b] stride 32, 16384 floats
    float* ws = sm + 16384;      // [row][k] 32 x 512
    int cid = blockIdx.x;
    int dir = cid >> 6;
    int j0 = (cid & 63) * 8;
    const float* w = dir ? w_hh_b : w_hh_f;
    int tid = threadIdx.x;

    // load W slice once: row r -> gate r>>3, unit j0+(r&7)
    for (int q = tid; q < 4096; q += 256) {
        int row = q >> 7, k4 = q & 127;
        int grow = (row >> 3) * Hq + j0 + (row & 7);
        *(float4*)&ws[row * 512 + k4 * 4] =
            *(const float4*)&w[grow * Hq + k4 * 4];
    }

    int b = tid & 31, jl = tid >> 5;          // jl == warp id
    const float4* wg0 = (const float4*)&ws[(0 * 8 + jl) * 512];
    const float4* wg1 = (const float4*)&ws[(1 * 8 + jl) * 512];
    const float4* wg2 = (const float4*)&ws[(2 * 8 + jl) * 512];
    const float4* wg3 = (const float4*)&ws[(3 * 8 + jl) * 512];
    volatile unsigned* bar = &g_bar[dir];
    float cprev = 0.f;

    for (int t = 0; t < Sq; t++) {
        int s = dir ? (Sq - 1 - t) : t;
        int prev_slot = dir ? (s + 1) : s;
        int out_slot = dir ? s : (s + 1);

        // prefetch xw (latency overlaps staging)
        const float* xwp = &g_XW[dir][b * Sq + s][j0 + jl];
        float xw0 = xwp[0 * Hq], xw1 = xwp[1 * Hq];
        float xw2 = xwp[2 * Hq], xw3 = xwp[3 * Hq];

        // stage h_prev: contiguous 64 KB, already [k][b]
        {
            const float4* src = (const float4*)&g_Ht[dir][prev_slot][0][0];
            float4* dst = (float4*)hs;
#pragma unroll
            for (int i = 0; i < 16; i++)
                dst[tid + i * 256] = src[tid + i * 256];
        }
        __syncthreads();

        float a0 = 0.f, a1 = 0.f, a2 = 0.f, a3 = 0.f;
#pragma unroll 4
        for (int k4 = 0; k4 < 128; k4++) {
            float4 w0 = wg0[k4];
            float4 w1 = wg1[k4];
            float4 w2 = wg2[k4];
            float4 w3 = wg3[k4];
            float h0 = hs[(k4 * 4 + 0) * 32 + b];
            float h1 = hs[(k4 * 4 + 1) * 32 + b];
            float h2 = hs[(k4 * 4 + 2) * 32 + b];
            float h3 = hs[(k4 * 4 + 3) * 32 + b];
            a0 = fmaf(w0.x, h0, a0); a1 = fmaf(w1.x, h0, a1);
            a2 = fmaf(w2.x, h0, a2); a3 = fmaf(w3.x, h0, a3);
            a0 = fmaf(w0.y, h1, a0); a1 = fmaf(w1.y, h1, a1);
            a2 = fmaf(w2.y, h1, a2); a3 = fmaf(w3.y, h1, a3);
            a0 = fmaf(w0.z, h2, a0); a1 = fmaf(w1.z, h2, a1);
            a2 = fmaf(w2.z, h2, a2); a3 = fmaf(w3.z, h2, a3);
            a0 = fmaf(w0.w, h3, a0); a1 = fmaf(w1.w, h3, a1);
            a2 = fmaf(w2.w, h3, a2); a3 = fmaf(w3.w, h3, a3);
        }

        float gi = a0 + xw0, gf = a1 + xw1, gg = a2 + xw2, go = a3 + xw3;
        float ig = 1.f / (1.f + expf(-gi));
        float fg = 1.f / (1.f + expf(-gf));
        float og = 1.f / (1.f + expf(-go));
        float c = fg * cprev + ig * tanhf(gg);
        float h = og * tanhf(c);
        cprev = c;
        g_H[dir][b][out_slot][j0 + jl] = h;            // for emission
        g_Ht[dir][out_slot][j0 + jl][b] = h;           // coalesced, next step

        // per-direction grid barrier (64 CTAs)
        __threadfence();
        __syncthreads();
        if (tid == 0) {
            atomicAdd((unsigned*)bar, 1u);
            unsigned target = (unsigned)(t + 1) * 64u;
            while (*bar < target) {}
        }
        __syncthreads();
    }
}

// ---------------- K3: emission logits -> e = exp ----------------
// 512 CTAs x 32 rows; K=1024 in 8 chunks of 128; all operands via smem.
__global__ __launch_bounds__(256) void emis_kernel(
    const float* __restrict__ w_em, const float* __restrict__ b_em)
{
    __shared__ float hsm[128 * 32];   // [k][row]
    __shared__ float wsm[128 * 48];   // [k][l]
    int m0 = blockIdx.x * 32;
    int tid = threadIdx.x;
    int row = tid & 31, lg = tid >> 5;    // 8 groups x 6 labels
    float acc[6];
#pragma unroll
    for (int c = 0; c < 6; c++) acc[c] = 0.f;

    for (int kc = 0; kc < 8; kc++) {
        __syncthreads();
        // stage h chunk: 32 rows x 128 k, transposed
        for (int q = tid; q < 1024; q += 256) {
            int rl = q >> 5, k4 = q & 31;
            int m = m0 + rl, bb = m >> 9, sidx = m & 511;
            int k = kc * 128 + k4 * 4;
            const float* src = (k < Hq) ? &g_H[0][bb][sidx + 1][k]
                                        : &g_H[1][bb][sidx][k - Hq];
            float4 v = *(const float4*)src;
            hsm[(k4 * 4 + 0) * 32 + rl] = v.x;
            hsm[(k4 * 4 + 1) * 32 + rl] = v.y;
            hsm[(k4 * 4 + 2) * 32 + rl] = v.z;
            hsm[(k4 * 4 + 3) * 32 + rl] = v.w;
        }
        // stage w chunk: 48 labels x 128 k, transposed
        for (int q = tid; q < 1536; q += 256) {
            int l = q >> 5, k4 = q & 31;
            float4 v = *(const float4*)&w_em[l * (2 * Hq) + kc * 128 + k4 * 4];
            wsm[(k4 * 4 + 0) * 48 + l] = v.x;
            wsm[(k4 * 4 + 1) * 48 + l] = v.y;
            wsm[(k4 * 4 + 2) * 48 + l] = v.z;
            wsm[(k4 * 4 + 3) * 48 + l] = v.w;
        }
        __syncthreads();
#pragma unroll 4
        for (int k = 0; k < 128; k++) {
            float hv = hsm[k * 32 + row];
            const float2* wp = (const float2*)&wsm[k * 48 + lg * 6];
            float2 w01 = wp[0], w23 = wp[1], w45 = wp[2];
            acc[0] = fmaf(hv, w01.x, acc[0]);
            acc[1] = fmaf(hv, w01.y, acc[1]);
            acc[2] = fmaf(hv, w23.x, acc[2]);
            acc[3] = fmaf(hv, w23.y, acc[3]);
            acc[4] = fmaf(hv, w45.x, acc[4]);
            acc[5] = fmaf(hv, w45.y, acc[5]);
        }
    }
    int m = m0 + row;
#pragma unroll
    for (int c = 0; c < 6; c++) {
        int l = lg * 6 + c;
        g_E[m][l] = expf(acc[c] + b_em[l]);
    }
}

// ---------------- K4: CRF partial sums (separable scan) ----------------
__global__ __launch_bounds__(64) void vpart_kernel(
    const float* __restrict__ transition, const int* __restrict__ length)
{
    __shared__ float ET[Lq * Lq];   // exp(exp(transition))
    __shared__ float erow[Lq];
    __shared__ float wrow[Lq];
    int b = blockIdx.x, chunk = blockIdx.y;
    int tid = threadIdx.x;
    int len = length[b];
    for (int idx = tid; idx < Lq * Lq; idx += 64)
        ET[idx] = expf(expf(transition[idx]));
    float vacc = 0.f;
    int t0 = chunk * 64;
    for (int tt = 0; tt < 64; tt++) {
        int t = t0 + tt;
        if (t >= len) break;
        __syncthreads();
        if (t == 0) continue;
        if (tid < Lq) erow[tid] = g_E[b * Sq + t][tid];
        __syncthreads();
        float m = -1e30f;
        for (int j = 0; j < Lq; j++) m = fmaxf(m, erow[j]);
        if (tid < Lq) wrow[tid] = expf(erow[tid] - m);
        __syncthreads();
        if (tid < Lq) {
            float dot = 0.f;
            const float* et = &ET[tid * Lq];
            for (int j = 0; j < Lq; j++) dot = fmaf(et[j], wrow[j], dot);
            vacc += m + logf(dot);
        }
    }
    if (tid < Lq) g_vpart[b][chunk][tid] = vacc;
}

// ---------------- K5: finalize ----------------
__global__ __launch_bounds__(256) void final_kernel(
    const int* __restrict__ labels, const int* __restrict__ length,
    const float* __restrict__ transition, float* __restrict__ out)
{
    __shared__ float sal[Lq];
    __shared__ float red[256];
    int b = blockIdx.x, tid = threadIdx.x;
    int len = length[b];
    if (tid < Lq) {
        float a = g_E[b * Sq][tid];
        for (int c = 0; c < 8; c++) a += g_vpart[b][c][tid];
        sal[tid] = a;
    }
    const int* lab = &labels[b * Sq];
    float r = 0.f;
    for (int s = tid; s < Sq; s += 256) {
        if (s < len) {
            r += g_E[b * Sq + s][lab[s]];
            if (s >= 1) r += expf(transition[lab[s - 1] * Lq + lab[s]]);
        }
    }
    red[tid] = r;
    __syncthreads();
    for (int off = 128; off > 0; off >>= 1) {
        if (tid < off) red[tid] += red[tid + off];
        __syncthreads();
    }
    if (tid == 0) {
        float m = -1e30f;
        for (int j = 0; j < Lq; j++) m = fmaxf(m, sal[j]);
        float ss = 0.f;
        for (int j = 0; j < Lq; j++) ss += expf(sal[j] - m);
        out[b] = m + logf(ss) - red[0];
    }
}

extern "C" void kernel_launch(void* const* d_in, const int* in_sizes, int n_in,
                              void* d_out, int out_size)
{
    const int*   tokens     = (const int*)d_in[0];
    const int*   length     = (const int*)d_in[1];
    const int*   labels     = (const int*)d_in[2];
    const float* embed      = (const float*)d_in[3];
    const float* w_ih_f     = (const float*)d_in[4];
    const float* w_hh_f     = (const float*)d_in[5];
    const float* b_f        = (const float*)d_in[6];
    const float* w_ih_b     = (const float*)d_in[7];
    const float* w_hh_b     = (const float*)d_in[8];
    const float* b_b        = (const float*)d_in[9];
    const float* w_em       = (const float*)d_in[10];
    const float* b_em       = (const float*)d_in[11];
    const float* transition = (const float*)d_in[12];
    float* out = (float*)d_out;

    const int persist_smem = (16384 + 16384) * 4;   // 131072 B
    static bool attr_done = false;
    if (!attr_done) {
        cudaFuncSetAttribute(lstm_persist,
            cudaFuncAttributeMaxDynamicSharedMemorySize, persist_smem);
        attr_done = true;
    }

    init_kernel<<<64, 256>>>();
    proj_kernel<<<dim3(128, 32, 2), 256>>>(tokens, embed, w_ih_f, b_f, w_ih_b, b_b);
    lstm_persist<<<128, 256, persist_smem>>>(w_hh_f, w_hh_b);
    emis_kernel<<<512, 256>>>(w_em, b_em);
    vpart_kernel<<<dim3(32, 8), 64>>>(transition, length);
    final_kernel<<<32, 256>>>(labels, length, transition, out);
}

// round 16
// speedup vs baseline: 1.0150x; 1.0150x over previous
#include <cuda_runtime.h>
#include <math.h>

#define Bq 32
#define Sq 512
#define Eq 256
#define Hq 512
#define Lq 48
#define Mq (Bq*Sq)

// ---------------- scratch ----------------
__device__ __align__(16) float g_XW[2][Mq][2048];
__device__ __align__(16) float g_H[2][Bq][Sq + 1][Hq];      // for emission
__device__ __align__(16) float g_Ht[2][Sq + 1][Hq][Bq];     // transposed, recurrence staging
__device__ __align__(16) float g_E[Mq][Lq];
__device__ float g_vpart[Bq][8][Lq];
__device__ unsigned g_barh[2][2];    // [dir][half]

// ---------------- init ----------------
__global__ void init_kernel() {
    int idx = blockIdx.x * blockDim.x + threadIdx.x;
    ((float*)g_Ht[0][0])[idx]  = 0.f;
    ((float*)g_Ht[1][Sq])[idx] = 0.f;
    if (idx < 4) ((unsigned*)g_barh)[idx] = 0u;
}

// ---------------- K1: embed-gather + input projection ----------------
// 128m x 64g tile, 256 threads, 8x4 thread tile, K chunks of 32.
__global__ __launch_bounds__(256) void proj_kernel(
    const int* __restrict__ tokens, const float* __restrict__ embed,
    const float* __restrict__ w_ih_f, const float* __restrict__ b_f,
    const float* __restrict__ w_ih_b, const float* __restrict__ b_b)
{
    __shared__ float xs[32 * 128];   // [k][m]
    __shared__ float ws[32 * 64];    // [k][g]
    __shared__ int toks[128];
    int dir = blockIdx.z;
    const float* w = dir ? w_ih_b : w_ih_f;
    const float* bias = dir ? b_b : b_f;
    int m0 = blockIdx.x * 128, g0 = blockIdx.y * 64;
    int tid = threadIdx.x;
    if (tid < 128) toks[tid] = tokens[m0 + tid];
    int tx = tid & 15, ty = tid >> 4;
    float acc[8][4];
#pragma unroll
    for (int a = 0; a < 8; a++)
#pragma unroll
        for (int c = 0; c < 4; c++) acc[a][c] = 0.f;
    for (int kc = 0; kc < 8; kc++) {
        __syncthreads();
        for (int q = tid; q < 1024; q += 256) {
            int ml = q >> 3, k4 = q & 7;
            float4 v = *(const float4*)&embed[toks[ml] * Eq + kc * 32 + k4 * 4];
            xs[(k4 * 4 + 0) * 128 + ml] = v.x; xs[(k4 * 4 + 1) * 128 + ml] = v.y;
            xs[(k4 * 4 + 2) * 128 + ml] = v.z; xs[(k4 * 4 + 3) * 128 + ml] = v.w;
        }
        for (int q = tid; q < 512; q += 256) {
            int gl = q >> 3, k4 = q & 7;
            float4 v = *(const float4*)&w[(g0 + gl) * Eq + kc * 32 + k4 * 4];
            ws[(k4 * 4 + 0) * 64 + gl] = v.x; ws[(k4 * 4 + 1) * 64 + gl] = v.y;
            ws[(k4 * 4 + 2) * 64 + gl] = v.z; ws[(k4 * 4 + 3) * 64 + gl] = v.w;
        }
        __syncthreads();
        const float4* xs4 = (const float4*)xs;
        const float4* ws4 = (const float4*)ws;
#pragma unroll 4
        for (int k = 0; k < 32; k++) {
            float4 x0 = xs4[k * 32 + tx];
            float4 x1 = xs4[k * 32 + 16 + tx];
            float4 wv = ws4[k * 16 + ty];
            float xr[8] = {x0.x, x0.y, x0.z, x0.w, x1.x, x1.y, x1.z, x1.w};
            float wr[4] = {wv.x, wv.y, wv.z, wv.w};
#pragma unroll
            for (int a = 0; a < 8; a++)
#pragma unroll
                for (int c = 0; c < 4; c++)
                    acc[a][c] = fmaf(xr[a], wr[c], acc[a][c]);
        }
    }
#pragma unroll
    for (int a = 0; a < 8; a++) {
        int m = m0 + (a < 4 ? tx * 4 + a : 64 + tx * 4 + (a - 4));
        int g = g0 + ty * 4;
        float4 o;
        o.x = acc[a][0] + bias[g + 0]; o.y = acc[a][1] + bias[g + 1];
        o.z = acc[a][2] + bias[g + 2]; o.w = acc[a][3] + bias[g + 3];
        *(float4*)&g_XW[dir][m][g] = o;
    }
}

// ---------------- K2: persistent bi-LSTM recurrence ----------------
// 128 CTAs (64 j-tiles x 2 dirs), 256 threads, ~136 KB smem.
// R12-proven 2x2 mainloop + half-step pipelined grid barrier.
#define WST 516
__global__ __launch_bounds__(256) void lstm_persist(
    const float* __restrict__ w_hh_f, const float* __restrict__ w_hh_b)
{
    extern __shared__ float sm[];
    float* hs = sm;                       // [k][b] stride 32, 16384 floats
    float* ws = sm + 16384;               // 32 rows x WST
    float* gsum = sm + 16384 + 32 * WST;  // 32 x 32
    int cid = blockIdx.x;
    int dir = cid >> 6;
    int jt = cid & 63;
    int j0 = jt * 8;
    int myhalf = jt >> 5;                 // producer half of this CTA
    const float* w = dir ? w_hh_b : w_hh_f;
    int tid = threadIdx.x;

    for (int q = tid; q < 4096; q += 256) {
        int row = q >> 7, k4 = q & 127;
        int grow = (row >> 3) * Hq + j0 + (row & 7);
        *(float4*)&ws[row * WST + k4 * 4] =
            *(const float4*)&w[grow * Hq + k4 * 4];
    }

    int eb = tid & 31, ejl = tid >> 5;    // epilogue mapping
    int r2 = tid >> 4, b2 = tid & 15;     // compute mapping (2x2)
    int ra = 2 * r2;
    const float4* wa4 = (const float4*)&ws[ra * WST];
    const float4* wb4 = (const float4*)&ws[(ra + 1) * WST];
    const float2* hp2 = (const float2*)hs;
    float cprev = 0.f;

    for (int t = 0; t < Sq; t++) {
        int s = dir ? (Sq - 1 - t) : t;
        int prev_slot = dir ? (s + 1) : s;
        int out_slot = dir ? s : (s + 1);

        const float* xwp = &g_XW[dir][eb * Sq + s][j0 + ejl];
        float xw0 = xwp[0 * Hq], xw1 = xwp[1 * Hq];
        float xw2 = xwp[2 * Hq], xw3 = xwp[3 * Hq];

        unsigned tgt = (unsigned)t * 32u;
        // ---- half 0: wait, stage K[0:256), compute k4 0..63 ----
        if (tid == 0)
            while (*(volatile unsigned*)&g_barh[dir][0] < tgt) {}
        __syncthreads();
        {
            const float4* src = (const float4*)&g_Ht[dir][prev_slot][0][0];
            float4* dst = (float4*)hs;
#pragma unroll
            for (int i = 0; i < 8; i++)
                dst[tid + i * 256] = src[tid + i * 256];
        }
        __syncthreads();
        float a00 = 0.f, a01 = 0.f, a10 = 0.f, a11 = 0.f;
#pragma unroll 4
        for (int k4 = 0; k4 < 64; k4++) {
            float4 wva = wa4[k4];
            float4 wvb = wb4[k4];
            float2 h0 = hp2[(k4 * 4 + 0) * 16 + b2];
            float2 h1 = hp2[(k4 * 4 + 1) * 16 + b2];
            float2 h2 = hp2[(k4 * 4 + 2) * 16 + b2];
            float2 h3 = hp2[(k4 * 4 + 3) * 16 + b2];
            a00 = fmaf(wva.x, h0.x, a00); a01 = fmaf(wva.x, h0.y, a01);
            a10 = fmaf(wvb.x, h0.x, a10); a11 = fmaf(wvb.x, h0.y, a11);
            a00 = fmaf(wva.y, h1.x, a00); a01 = fmaf(wva.y, h1.y, a01);
            a10 = fmaf(wvb.y, h1.x, a10); a11 = fmaf(wvb.y, h1.y, a11);
            a00 = fmaf(wva.z, h2.x, a00); a01 = fmaf(wva.z, h2.y, a01);
            a10 = fmaf(wvb.z, h2.x, a10); a11 = fmaf(wvb.z, h2.y, a11);
            a00 = fmaf(wva.w, h3.x, a00); a01 = fmaf(wva.w, h3.y, a01);
            a10 = fmaf(wvb.w, h3.x, a10); a11 = fmaf(wvb.w, h3.y, a11);
        }
        // ---- half 1: wait, stage K[256:512), compute k4 64..127 ----
        if (tid == 0)
            while (*(volatile unsigned*)&g_barh[dir][1] < tgt) {}
        __syncthreads();
        {
            const float4* src = (const float4*)&g_Ht[dir][prev_slot][256][0];
            float4* dst = (float4*)(hs + 8192);
#pragma unroll
            for (int i = 0; i < 8; i++)
                dst[tid + i * 256] = src[tid + i * 256];
        }
        __syncthreads();
#pragma unroll 4
        for (int k4 = 64; k4 < 128; k4++) {
            float4 wva = wa4[k4];
            float4 wvb = wb4[k4];
            float2 h0 = hp2[(k4 * 4 + 0) * 16 + b2];
            float2 h1 = hp2[(k4 * 4 + 1) * 16 + b2];
            float2 h2 = hp2[(k4 * 4 + 2) * 16 + b2];
            float2 h3 = hp2[(k4 * 4 + 3) * 16 + b2];
            a00 = fmaf(wva.x, h0.x, a00); a01 = fmaf(wva.x, h0.y, a01);
            a10 = fmaf(wvb.x, h0.x, a10); a11 = fmaf(wvb.x, h0.y, a11);
            a00 = fmaf(wva.y, h1.x, a00); a01 = fmaf(wva.y, h1.y, a01);
            a10 = fmaf(wvb.y, h1.x, a10); a11 = fmaf(wvb.y, h1.y, a11);
            a00 = fmaf(wva.z, h2.x, a00); a01 = fmaf(wva.z, h2.y, a01);
            a10 = fmaf(wvb.z, h2.x, a10); a11 = fmaf(wvb.z, h2.y, a11);
            a00 = fmaf(wva.w, h3.x, a00); a01 = fmaf(wva.w, h3.y, a01);
            a10 = fmaf(wvb.w, h3.x, a10); a11 = fmaf(wvb.w, h3.y, a11);
        }
        // gate sums -> gsum (separate region; prev step's reads fenced by end-of-step sync)
        *(float2*)&gsum[ra * 32 + 2 * b2] = make_float2(a00, a01);
        *(float2*)&gsum[(ra + 1) * 32 + 2 * b2] = make_float2(a10, a11);
        __syncthreads();

        float gi = gsum[(0 * 8 + ejl) * 32 + eb] + xw0;
        float gf = gsum[(1 * 8 + ejl) * 32 + eb] + xw1;
        float gg = gsum[(2 * 8 + ejl) * 32 + eb] + xw2;
        float go = gsum[(3 * 8 + ejl) * 32 + eb] + xw3;
        float ig = 1.f / (1.f + expf(-gi));
        float fg = 1.f / (1.f + expf(-gf));
        float og = 1.f / (1.f + expf(-go));
        float c = fg * cprev + ig * tanhf(gg);
        float h = og * tanhf(c);
        cprev = c;
        g_H[dir][eb][out_slot][j0 + ejl] = h;
        g_Ht[dir][out_slot][j0 + ejl][eb] = h;

        __threadfence();
        __syncthreads();
        if (tid == 0) atomicAdd(&g_barh[dir][myhalf], 1u);
    }
}

// ---------------- K3: emission logits -> e = exp ----------------
// 256 CTAs x 64 rows; 2-row x 6-label thread tile; conflict-free staging.
__global__ __launch_bounds__(256) void emis_kernel(
    const float* __restrict__ w_em, const float* __restrict__ b_em)
{
    __shared__ float hsm[128 * 64];   // [k][row], 32 KB
    __shared__ float wsm[128 * 48];   // [k][l],   24 KB
    int m0 = blockIdx.x * 64;
    int tid = threadIdx.x;
    int rp = tid & 31, lg = tid >> 5;
    float acc[2][6];
#pragma unroll
    for (int a = 0; a < 2; a++)
#pragma unroll
        for (int c = 0; c < 6; c++) acc[a][c] = 0.f;

    for (int kc = 0; kc < 8; kc++) {
        __syncthreads();
        // h chunk: lanes -> consecutive rows (conflict-free STS)
        for (int q = tid; q < 2048; q += 256) {
            int k4 = q >> 6, rl = q & 63;
            int m = m0 + rl, bb = m >> 9, sidx = m & 511;
            int k = kc * 128 + k4 * 4;
            const float* src = (k < Hq) ? &g_H[0][bb][sidx + 1][k]
                                        : &g_H[1][bb][sidx][k - Hq];
            float4 v = *(const float4*)src;
            hsm[(k4 * 4 + 0) * 64 + rl] = v.x;
            hsm[(k4 * 4 + 1) * 64 + rl] = v.y;
            hsm[(k4 * 4 + 2) * 64 + rl] = v.z;
            hsm[(k4 * 4 + 3) * 64 + rl] = v.w;
        }
        // w chunk: lanes -> consecutive labels
        for (int q = tid; q < 1536; q += 256) {
            int k4 = q / 48, l = q % 48;
            float4 v = *(const float4*)&w_em[l * (2 * Hq) + kc * 128 + k4 * 4];
            wsm[(k4 * 4 + 0) * 48 + l] = v.x;
            wsm[(k4 * 4 + 1) * 48 + l] = v.y;
            wsm[(k4 * 4 + 2) * 48 + l] = v.z;
            wsm[(k4 * 4 + 3) * 48 + l] = v.w;
        }
        __syncthreads();
#pragma unroll 4
        for (int k = 0; k < 128; k++) {
            float2 hv = *(const float2*)&hsm[k * 64 + 2 * rp];
            const float2* wp = (const float2*)&wsm[k * 48 + lg * 6];
            float2 w01 = wp[0], w23 = wp[1], w45 = wp[2];
            acc[0][0] = fmaf(hv.x, w01.x, acc[0][0]);
            acc[1][0] = fmaf(hv.y, w01.x, acc[1][0]);
            acc[0][1] = fmaf(hv.x, w01.y, acc[0][1]);
            acc[1][1] = fmaf(hv.y, w01.y, acc[1][1]);
            acc[0][2] = fmaf(hv.x, w23.x, acc[0][2]);
            acc[1][2] = fmaf(hv.y, w23.x, acc[1][2]);
            acc[0][3] = fmaf(hv.x, w23.y, acc[0][3]);
            acc[1][3] = fmaf(hv.y, w23.y, acc[1][3]);
            acc[0][4] = fmaf(hv.x, w45.x, acc[0][4]);
            acc[1][4] = fmaf(hv.y, w45.x, acc[1][4]);
            acc[0][5] = fmaf(hv.x, w45.y, acc[0][5]);
            acc[1][5] = fmaf(hv.y, w45.y, acc[1][5]);
        }
    }
#pragma unroll
    for (int a = 0; a < 2; a++) {
        int m = m0 + 2 * rp + a;
#pragma unroll
        for (int c = 0; c < 6; c++) {
            int l = lg * 6 + c;
            g_E[m][l] = expf(acc[a][c] + b_em[l]);
        }
    }
}

// ---------------- K4: CRF partial sums (separable scan) ----------------
__global__ __launch_bounds__(64) void vpart_kernel(
    const float* __restrict__ transition, const int* __restrict__ length)
{
    __shared__ float ET[Lq * Lq];   // exp(exp(transition))
    __shared__ float erow[Lq];
    __shared__ float wrow[Lq];
    int b = blockIdx.x, chunk = blockIdx.y;
    int tid = threadIdx.x;
    int len = length[b];
    for (int idx = tid; idx < Lq * Lq; idx += 64)
        ET[idx] = expf(expf(transition[idx]));
    float vacc = 0.f;
    int t0 = chunk * 64;
    for (int tt = 0; tt < 64; tt++) {
        int t = t0 + tt;
        if (t >= len) break;
        __syncthreads();
        if (t == 0) continue;
        if (tid < Lq) erow[tid] = g_E[b * Sq + t][tid];
        __syncthreads();
        float m = -1e30f;
        for (int j = 0; j < Lq; j++) m = fmaxf(m, erow[j]);
        if (tid < Lq) wrow[tid] = expf(erow[tid] - m);
        __syncthreads();
        if (tid < Lq) {
            float dot = 0.f;
            const float* et = &ET[tid * Lq];
            for (int j = 0; j < Lq; j++) dot = fmaf(et[j], wrow[j], dot);
            vacc += m + logf(dot);
        }
    }
    if (tid < Lq) g_vpart[b][chunk][tid] = vacc;
}

// ---------------- K5: finalize ----------------
__global__ __launch_bounds__(256) void final_kernel(
    const int* __restrict__ labels, const int* __restrict__ length,
    const float* __restrict__ transition, float* __restrict__ out)
{
    __shared__ float sal[Lq];
    __shared__ float red[256];
    int b = blockIdx.x, tid = threadIdx.x;
    int len = length[b];
    if (tid < Lq) {
        float a = g_E[b * Sq][tid];
        for (int c = 0; c < 8; c++) a += g_vpart[b][c][tid];
        sal[tid] = a;
    }
    const int* lab = &labels[b * Sq];
    float r = 0.f;
    for (int s = tid; s < Sq; s += 256) {
        if (s < len) {
            r += g_E[b * Sq + s][lab[s]];
            if (s >= 1) r += expf(transition[lab[s - 1] * Lq + lab[s]]);
        }
    }
    red[tid] = r;
    __syncthreads();
    for (int off = 128; off > 0; off >>= 1) {
        if (tid < off) red[tid] += red[tid + off];
        __syncthreads();
    }
    if (tid == 0) {
        float m = -1e30f;
        for (int j = 0; j < Lq; j++) m = fmaxf(m, sal[j]);
        float ss = 0.f;
        for (int j = 0; j < Lq; j++) ss += expf(sal[j] - m);
        out[b] = m + logf(ss) - red[0];
    }
}

extern "C" void kernel_launch(void* const* d_in, const int* in_sizes, int n_in,
                              void* d_out, int out_size)
{
    const int*   tokens     = (const int*)d_in[0];
    const int*   length     = (const int*)d_in[1];
    const int*   labels     = (const int*)d_in[2];
    const float* embed      = (const float*)d_in[3];
    const float* w_ih_f     = (const float*)d_in[4];
    const float* w_hh_f     = (const float*)d_in[5];
    const float* b_f        = (const float*)d_in[6];
    const float* w_ih_b     = (const float*)d_in[7];
    const float* w_hh_b     = (const float*)d_in[8];
    const float* b_b        = (const float*)d_in[9];
    const float* w_em       = (const float*)d_in[10];
    const float* b_em       = (const float*)d_in[11];
    const float* transition = (const float*)d_in[12];
    float* out = (float*)d_out;

    const int persist_smem = (16384 + 32 * WST + 1024) * 4;   // 135,680 B
    cudaFuncSetAttribute(lstm_persist,
        cudaFuncAttributeMaxDynamicSharedMemorySize, persist_smem);

    init_kernel<<<64, 256>>>();
    proj_kernel<<<dim3(128, 32, 2), 256>>>(tokens, embed, w_ih_f, b_f, w_ih_b, b_b);
    lstm_persist<<<128, 256, persist_smem>>>(w_hh_f, w_hh_b);
    emis_kernel<<<256, 256>>>(w_em, b_em);
    vpart_kernel<<<dim3(32, 8), 64>>>(transition, length);
    final_kernel<<<32, 256>>>(labels, length, transition, out);
}

// round 17
// speedup vs baseline: 1.2387x; 1.2204x over previous
#include <cuda_runtime.h>
#include <math.h>

#define Bq 32
#define Sq 512
#define Eq 256
#define Hq 512
#define Lq 48
#define Mq (Bq*Sq)

// ---------------- scratch ----------------
__device__ __align__(16) float g_XW[2][Mq][2048];
__device__ __align__(16) float g_Ht[2][Sq + 1][Hq][Bq];   // h, transposed [k][b]
__device__ __align__(16) float g_E[Mq][Lq];
__device__ float g_vpart[Bq][8][Lq];
__device__ unsigned g_bar[2];

// ---------------- init ----------------
__global__ void init_kernel() {
    int idx = blockIdx.x * blockDim.x + threadIdx.x;
    ((float*)g_Ht[0][0])[idx]  = 0.f;
    ((float*)g_Ht[1][Sq])[idx] = 0.f;
    if (idx < 2) g_bar[idx] = 0u;
}

// ---------------- K1: embed-gather + input projection ----------------
// 128m x 64g tile, 256 threads, 8x4 thread tile, K chunks of 32.
__global__ __launch_bounds__(256) void proj_kernel(
    const int* __restrict__ tokens, const float* __restrict__ embed,
    const float* __restrict__ w_ih_f, const float* __restrict__ b_f,
    const float* __restrict__ w_ih_b, const float* __restrict__ b_b)
{
    __shared__ float xs[32 * 128];   // [k][m]
    __shared__ float ws[32 * 64];    // [k][g]
    __shared__ int toks[128];
    int dir = blockIdx.z;
    const float* w = dir ? w_ih_b : w_ih_f;
    const float* bias = dir ? b_b : b_f;
    int m0 = blockIdx.x * 128, g0 = blockIdx.y * 64;
    int tid = threadIdx.x;
    if (tid < 128) toks[tid] = tokens[m0 + tid];
    int tx = tid & 15, ty = tid >> 4;
    float acc[8][4];
#pragma unroll
    for (int a = 0; a < 8; a++)
#pragma unroll
        for (int c = 0; c < 4; c++) acc[a][c] = 0.f;
    for (int kc = 0; kc < 8; kc++) {
        __syncthreads();
        for (int q = tid; q < 1024; q += 256) {
            int ml = q >> 3, k4 = q & 7;
            float4 v = *(const float4*)&embed[toks[ml] * Eq + kc * 32 + k4 * 4];
            xs[(k4 * 4 + 0) * 128 + ml] = v.x; xs[(k4 * 4 + 1) * 128 + ml] = v.y;
            xs[(k4 * 4 + 2) * 128 + ml] = v.z; xs[(k4 * 4 + 3) * 128 + ml] = v.w;
        }
        for (int q = tid; q < 512; q += 256) {
            int gl = q >> 3, k4 = q & 7;
            float4 v = *(const float4*)&w[(g0 + gl) * Eq + kc * 32 + k4 * 4];
            ws[(k4 * 4 + 0) * 64 + gl] = v.x; ws[(k4 * 4 + 1) * 64 + gl] = v.y;
            ws[(k4 * 4 + 2) * 64 + gl] = v.z; ws[(k4 * 4 + 3) * 64 + gl] = v.w;
        }
        __syncthreads();
        const float4* xs4 = (const float4*)xs;
        const float4* ws4 = (const float4*)ws;
#pragma unroll 4
        for (int k = 0; k < 32; k++) {
            float4 x0 = xs4[k * 32 + tx];
            float4 x1 = xs4[k * 32 + 16 + tx];
            float4 wv = ws4[k * 16 + ty];
            float xr[8] = {x0.x, x0.y, x0.z, x0.w, x1.x, x1.y, x1.z, x1.w};
            float wr[4] = {wv.x, wv.y, wv.z, wv.w};
#pragma unroll
            for (int a = 0; a < 8; a++)
#pragma unroll
                for (int c = 0; c < 4; c++)
                    acc[a][c] = fmaf(xr[a], wr[c], acc[a][c]);
        }
    }
#pragma unroll
    for (int a = 0; a < 8; a++) {
        int m = m0 + (a < 4 ? tx * 4 + a : 64 + tx * 4 + (a - 4));
        int g = g0 + ty * 4;
        float4 o;
        o.x = acc[a][0] + bias[g + 0]; o.y = acc[a][1] + bias[g + 1];
        o.z = acc[a][2] + bias[g + 2]; o.w = acc[a][3] + bias[g + 3];
        *(float4*)&g_XW[dir][m][g] = o;
    }
}

// ---------------- K2: persistent bi-LSTM recurrence ----------------
// 128 CTAs (64 j-tiles x 2 dirs), 256 threads, ~136 KB smem.
// Single per-dir barrier (wait top / arrive bottom), register-split staging.
#define WST 516
__global__ __launch_bounds__(256) void lstm_persist(
    const float* __restrict__ w_hh_f, const float* __restrict__ w_hh_b)
{
    extern __shared__ float sm[];
    float* hs = sm;                       // [k][b] stride 32, 16384 floats
    float* ws = sm + 16384;               // 32 rows x WST
    float* gsum = sm + 16384 + 32 * WST;  // 32 x 32
    int cid = blockIdx.x;
    int dir = cid >> 6;
    int j0 = (cid & 63) * 8;
    const float* w = dir ? w_hh_b : w_hh_f;
    int tid = threadIdx.x;

    // load W slice once: row r -> gate r>>3, unit j0+(r&7)
    for (int q = tid; q < 4096; q += 256) {
        int row = q >> 7, k4 = q & 127;
        int grow = (row >> 3) * Hq + j0 + (row & 7);
        *(float4*)&ws[row * WST + k4 * 4] =
            *(const float4*)&w[grow * Hq + k4 * 4];
    }

    int eb = tid & 31, ejl = tid >> 5;    // epilogue mapping
    int r2 = tid >> 4, b2 = tid & 15;     // compute mapping (2x2)
    int ra = 2 * r2;
    const float4* wa4 = (const float4*)&ws[ra * WST];
    const float4* wb4 = (const float4*)&ws[(ra + 1) * WST];
    const float2* hp2 = (const float2*)hs;
    volatile unsigned* bar = &g_bar[dir];
    float cprev = 0.f;

    for (int t = 0; t < Sq; t++) {
        int s = dir ? (Sq - 1 - t) : t;
        int prev_slot = dir ? (s + 1) : s;
        int out_slot = dir ? s : (s + 1);

        const float* xwp = &g_XW[dir][eb * Sq + s][j0 + ejl];
        float xw0 = xwp[0 * Hq], xw1 = xwp[1 * Hq];
        float xw2 = xwp[2 * Hq], xw3 = xwp[3 * Hq];

        // wait for all CTAs of this dir to have finished step t-1
        if (tid == 0) {
            unsigned tgt = (unsigned)t * 64u;
            while (*bar < tgt) {}
        }
        __syncthreads();

        // staging: issue half-1 loads into regs first, then half-0 load+store
        const float4* src = (const float4*)&g_Ht[dir][prev_slot][0][0];
        float4* dst = (float4*)hs;
        float4 r1[8];
#pragma unroll
        for (int i = 0; i < 8; i++)
            r1[i] = src[2048 + tid + i * 256];
#pragma unroll
        for (int i = 0; i < 8; i++)
            dst[tid + i * 256] = src[tid + i * 256];
        __syncthreads();

        float a00 = 0.f, a01 = 0.f, a10 = 0.f, a11 = 0.f;
#pragma unroll 4
        for (int k4 = 0; k4 < 64; k4++) {
            float4 wva = wa4[k4];
            float4 wvb = wb4[k4];
            float2 h0 = hp2[(k4 * 4 + 0) * 16 + b2];
            float2 h1 = hp2[(k4 * 4 + 1) * 16 + b2];
            float2 h2 = hp2[(k4 * 4 + 2) * 16 + b2];
            float2 h3 = hp2[(k4 * 4 + 3) * 16 + b2];
            a00 = fmaf(wva.x, h0.x, a00); a01 = fmaf(wva.x, h0.y, a01);
            a10 = fmaf(wvb.x, h0.x, a10); a11 = fmaf(wvb.x, h0.y, a11);
            a00 = fmaf(wva.y, h1.x, a00); a01 = fmaf(wva.y, h1.y, a01);
            a10 = fmaf(wvb.y, h1.x, a10); a11 = fmaf(wvb.y, h1.y, a11);
            a00 = fmaf(wva.z, h2.x, a00); a01 = fmaf(wva.z, h2.y, a01);
            a10 = fmaf(wvb.z, h2.x, a10); a11 = fmaf(wvb.z, h2.y, a11);
            a00 = fmaf(wva.w, h3.x, a00); a01 = fmaf(wva.w, h3.y, a01);
            a10 = fmaf(wvb.w, h3.x, a10); a11 = fmaf(wvb.w, h3.y, a11);
        }
        // store half-1 (long since arrived), then finish
#pragma unroll
        for (int i = 0; i < 8; i++)
            dst[2048 + tid + i * 256] = r1[i];
        __syncthreads();
#pragma unroll 4
        for (int k4 = 64; k4 < 128; k4++) {
            float4 wva = wa4[k4];
            float4 wvb = wb4[k4];
            float2 h0 = hp2[(k4 * 4 + 0) * 16 + b2];
            float2 h1 = hp2[(k4 * 4 + 1) * 16 + b2];
            float2 h2 = hp2[(k4 * 4 + 2) * 16 + b2];
            float2 h3 = hp2[(k4 * 4 + 3) * 16 + b2];
            a00 = fmaf(wva.x, h0.x, a00); a01 = fmaf(wva.x, h0.y, a01);
            a10 = fmaf(wvb.x, h0.x, a10); a11 = fmaf(wvb.x, h0.y, a11);
            a00 = fmaf(wva.y, h1.x, a00); a01 = fmaf(wva.y, h1.y, a01);
            a10 = fmaf(wvb.y, h1.x, a10); a11 = fmaf(wvb.y, h1.y, a11);
            a00 = fmaf(wva.z, h2.x, a00); a01 = fmaf(wva.z, h2.y, a01);
            a10 = fmaf(wvb.z, h2.x, a10); a11 = fmaf(wvb.z, h2.y, a11);
            a00 = fmaf(wva.w, h3.x, a00); a01 = fmaf(wva.w, h3.y, a01);
            a10 = fmaf(wvb.w, h3.x, a10); a11 = fmaf(wvb.w, h3.y, a11);
        }

        *(float2*)&gsum[ra * 32 + 2 * b2] = make_float2(a00, a01);
        *(float2*)&gsum[(ra + 1) * 32 + 2 * b2] = make_float2(a10, a11);
        __syncthreads();

        float gi = gsum[(0 * 8 + ejl) * 32 + eb] + xw0;
        float gf = gsum[(1 * 8 + ejl) * 32 + eb] + xw1;
        float gg = gsum[(2 * 8 + ejl) * 32 + eb] + xw2;
        float go = gsum[(3 * 8 + ejl) * 32 + eb] + xw3;
        float ig = 1.f / (1.f + expf(-gi));
        float fg = 1.f / (1.f + expf(-gf));
        float og = 1.f / (1.f + expf(-go));
        float c = fg * cprev + ig * tanhf(gg);
        float h = og * tanhf(c);
        cprev = c;
        g_Ht[dir][out_slot][j0 + ejl][eb] = h;   // coalesced (lanes = eb)

        __threadfence();
        __syncthreads();
        if (tid == 0) atomicAdd((unsigned*)bar, 1u);
    }
}

// ---------------- K3: emission logits -> e = exp ----------------
// 512 CTAs (one per s), 32 b-rows each; h staged by pure memcpy from g_Ht.
__global__ __launch_bounds__(256) void emis_kernel(
    const float* __restrict__ w_em, const float* __restrict__ b_em)
{
    __shared__ float hsm[128 * 32];   // [k][b], 16 KB
    __shared__ float wsm[128 * 48];   // [k][l], 24 KB
    int s = blockIdx.x;
    int tid = threadIdx.x;
    int b = tid & 31, lg = tid >> 5;   // 8 groups x 6 labels
    float acc[6];
#pragma unroll
    for (int c = 0; c < 6; c++) acc[c] = 0.f;

    for (int kc = 0; kc < 8; kc++) {
        __syncthreads();
        // h chunk: contiguous 16 KB from g_Ht
        const float4* src = (kc < 4)
            ? (const float4*)&g_Ht[0][s + 1][kc * 128][0]
            : (const float4*)&g_Ht[1][s][(kc - 4) * 128][0];
        float4* dst = (float4*)hsm;
#pragma unroll
        for (int i = 0; i < 4; i++)
            dst[tid + i * 256] = src[tid + i * 256];
        // w chunk: 48 labels x 128 k, transposed
        for (int q = tid; q < 1536; q += 256) {
            int k4 = q / 48, l = q % 48;
            float4 v = *(const float4*)&w_em[l * (2 * Hq) + kc * 128 + k4 * 4];
            wsm[(k4 * 4 + 0) * 48 + l] = v.x;
            wsm[(k4 * 4 + 1) * 48 + l] = v.y;
            wsm[(k4 * 4 + 2) * 48 + l] = v.z;
            wsm[(k4 * 4 + 3) * 48 + l] = v.w;
        }
        __syncthreads();
#pragma unroll 4
        for (int k = 0; k < 128; k++) {
            float hv = hsm[k * 32 + b];
            const float2* wp = (const float2*)&wsm[k * 48 + lg * 6];
            float2 w01 = wp[0], w23 = wp[1], w45 = wp[2];
            acc[0] = fmaf(hv, w01.x, acc[0]);
            acc[1] = fmaf(hv, w01.y, acc[1]);
            acc[2] = fmaf(hv, w23.x, acc[2]);
            acc[3] = fmaf(hv, w23.y, acc[3]);
            acc[4] = fmaf(hv, w45.x, acc[4]);
            acc[5] = fmaf(hv, w45.y, acc[5]);
        }
    }
    int m = b * Sq + s;
    float* ep = &g_E[m][lg * 6];
#pragma unroll
    for (int c = 0; c < 3; c++) {
        float2 o;
        o.x = expf(acc[2 * c + 0] + b_em[lg * 6 + 2 * c + 0]);
        o.y = expf(acc[2 * c + 1] + b_em[lg * 6 + 2 * c + 1]);
        *(float2*)&ep[2 * c] = o;
    }
}

// ---------------- K4: CRF partial sums (separable scan) ----------------
__global__ __launch_bounds__(64) void vpart_kernel(
    const float* __restrict__ transition, const int* __restrict__ length)
{
    __shared__ float ET[Lq * Lq];   // exp(exp(transition))
    __shared__ float erow[Lq];
    __shared__ float wrow[Lq];
    int b = blockIdx.x, chunk = blockIdx.y;
    int tid = threadIdx.x;
    int len = length[b];
    for (int idx = tid; idx < Lq * Lq; idx += 64)
        ET[idx] = expf(expf(transition[idx]));
    float vacc = 0.f;
    int t0 = chunk * 64;
    for (int tt = 0; tt < 64; tt++) {
        int t = t0 + tt;
        if (t >= len) break;
        __syncthreads();
        if (t == 0) continue;
        if (tid < Lq) erow[tid] = g_E[b * Sq + t][tid];
        __syncthreads();
        float m = -1e30f;
        for (int j = 0; j < Lq; j++) m = fmaxf(m, erow[j]);
        if (tid < Lq) wrow[tid] = expf(erow[tid] - m);
        __syncthreads();
        if (tid < Lq) {
            float dot = 0.f;
            const float* et = &ET[tid * Lq];
            for (int j = 0; j < Lq; j++) dot = fmaf(et[j], wrow[j], dot);
            vacc += m + logf(dot);
        }
    }
    if (tid < Lq) g_vpart[b][chunk][tid] = vacc;
}

// ---------------- K5: finalize ----------------
__global__ __launch_bounds__(256) void final_kernel(
    const int* __restrict__ labels, const int* __restrict__ length,
    const float* __restrict__ transition, float* __restrict__ out)
{
    __shared__ float sal[Lq];
    __shared__ float red[256];
    int b = blockIdx.x, tid = threadIdx.x;
    int len = length[b];
    if (tid < Lq) {
        float a = g_E[b * Sq][tid];
        for (int c = 0; c < 8; c++) a += g_vpart[b][c][tid];
        sal[tid] = a;
    }
    const int* lab = &labels[b * Sq];
    float r = 0.f;
    for (int s = tid; s < Sq; s += 256) {
        if (s < len) {
            r += g_E[b * Sq + s][lab[s]];
            if (s >= 1) r += expf(transition[lab[s - 1] * Lq + lab[s]]);
        }
    }
    red[tid] = r;
    __syncthreads();
    for (int off = 128; off > 0; off >>= 1) {
        if (tid < off) red[tid] += red[tid + off];
        __syncthreads();
    }
    if (tid == 0) {
        float m = -1e30f;
        for (int j = 0; j < Lq; j++) m = fmaxf(m, sal[j]);
        float ss = 0.f;
        for (int j = 0; j < Lq; j++) ss += expf(sal[j] - m);
        out[b] = m + logf(ss) - red[0];
    }
}

extern "C" void kernel_launch(void* const* d_in, const int* in_sizes, int n_in,
                              void* d_out, int out_size)
{
    const int*   tokens     = (const int*)d_in[0];
    const int*   length     = (const int*)d_in[1];
    const int*   labels     = (const int*)d_in[2];
    const float* embed      = (const float*)d_in[3];
    const float* w_ih_f     = (const float*)d_in[4];
    const float* w_hh_f     = (const float*)d_in[5];
    const float* b_f        = (const float*)d_in[6];
    const float* w_ih_b     = (const float*)d_in[7];
    const float* w_hh_b     = (const float*)d_in[8];
    const float* b_b        = (const float*)d_in[9];
    const float* w_em       = (const float*)d_in[10];
    const float* b_em       = (const float*)d_in[11];
    const float* transition = (const float*)d_in[12];
    float* out = (float*)d_out;

    const int persist_smem = (16384 + 32 * WST + 1024) * 4;   // 135,680 B
    cudaFuncSetAttribute(lstm_persist,
        cudaFuncAttributeMaxDynamicSharedMemorySize, persist_smem);

    init_kernel<<<64, 256>>>();
    proj_kernel<<<dim3(128, 32, 2), 256>>>(tokens, embed, w_ih_f, b_f, w_ih_b, b_b);
    lstm_persist<<<128, 256, persist_smem>>>(w_hh_f, w_hh_b);
    emis_kernel<<<512, 256>>>(w_em, b_em);
    vpart_kernel<<<dim3(32, 8), 64>>>(transition, length);
    final_kernel<<<32, 256>>>(labels, length, transition, out);
}